// round 6
// baseline (speedup 1.0000x reference)
#include <cuda_runtime.h>
#include <cstdint>

// out = LeakyReLU( D^-1 * (A @ (X @ W^T)) + b ),  B=32, N=1024, F=128
// Base-ISA tensor path (mma.sync m16n8k8 tf32 + cp.async).
//
// k_xw  : XW = X @ W^T (Markidis 3-term tf32 ~ fp32 accuracy). W split to tf32
//         hi/lo ONCE into conflict-free smem [k][o] (stride 136). Output written
//         in k_main's per-thread fragment order (64B chunks).
// k_main: C = A @ XW per batch, BM=64 (3 CTAs/SM); deg = rowsum(A) via FADD on
//         the idle fma pipe; epilogue leaky(C/deg + bias).
//
// Packed B layout (per batch, 131072 floats), for m(0..1023), o(0..127):
//   stage=m>>5, k=m&31
//   chunk = (o>>5)*64 + ((k>>4)&1)*32 + (o&7)*4 + (k&3)
//   float_in_chunk = ((k>>3)&1)*8 + ((o>>3)&3)*2 + ((k>>2)&1)
//   idx = stage*4096 + chunk*16 + float_in_chunk

#define NEG_SLOPE 0.01f

__device__ float g_xw[32u * 1024u * 128u];  // packed-fragment XW (16 MB)

// ---------------- helpers ----------------
__device__ __forceinline__ uint32_t su32(const void* p) {
    uint32_t r;
    asm("{\n\t.reg .u64 t;\n\tcvta.to.shared.u64 t, %1;\n\tcvt.u32.u64 %0, t;\n\t}"
        : "=r"(r) : "l"(p));
    return r;
}
__device__ __forceinline__ void cp16(uint32_t dst, const void* src) {
    asm volatile("cp.async.cg.shared.global [%0], [%1], 16;" :: "r"(dst), "l"(src));
}
__device__ __forceinline__ void cp_commit() {
    asm volatile("cp.async.commit_group;" ::: "memory");
}
template <int N>
__device__ __forceinline__ void cp_wait() {
    asm volatile("cp.async.wait_group %0;" :: "n"(N) : "memory");
}
__device__ __forceinline__ uint32_t tf32_rna(float x) {
    uint32_t r;
    asm("cvt.rna.tf32.f32 %0, %1;" : "=r"(r) : "f"(x));
    return r;
}
__device__ __forceinline__ void mma8(float* c, const uint32_t* a, const uint32_t* b) {
    asm volatile(
        "mma.sync.aligned.m16n8k8.row.col.f32.tf32.tf32.f32 "
        "{%0,%1,%2,%3}, {%4,%5,%6,%7}, {%8,%9}, {%0,%1,%2,%3};"
        : "+f"(c[0]), "+f"(c[1]), "+f"(c[2]), "+f"(c[3])
        : "r"(a[0]), "r"(a[1]), "r"(a[2]), "r"(a[3]), "r"(b[0]), "r"(b[1]));
}
__device__ __forceinline__ float leaky(float v) {
    return (v >= 0.0f) ? v : NEG_SLOPE * v;
}

#define AP 36    // A/X smem row pad: frag LDS bank = 4g+tig (bijective)
#define WS 136   // W hi/lo [k][o] stride: bank = 8*tig+g (bijective)

// =====================================================================
// k_xw: XW = X @ W^T.  grid=256 (m-tiles of 128), 256 threads, occ 1.
// smem floats: Whs[128*136] | Wls[128*136] | Xs[4][128][36]; staging
// reuses sm[0..16384) after the main loop.
// =====================================================================
#define XW_WL 17408
#define XW_X  34816
#define XW_SMEM ((34816 + 4 * 128 * AP) * 4)  // 212992 B

__global__ __launch_bounds__(256) void k_xw(const float* __restrict__ X,
                                            const float* __restrict__ W) {
    extern __shared__ float sm[];
    float* Whs = sm;
    float* Wls = sm + XW_WL;
    float* Xs  = sm + XW_X;
    const uint32_t xs_a = su32(Xs);

    const int tid = threadIdx.x, lane = tid & 31, wid = tid >> 5;
    const int g = lane >> 2, tig = lane & 3;
    const int wr = wid & 3, wc = wid >> 2;
    const int m0 = blockIdx.x * 128;

    // async-load whole X tile: 4 kt-blocks of [128][36]
#pragma unroll
    for (int i = 0; i < 16; i++) {
        int gi = tid + i * 256;
        int kt = gi >> 10, r = (gi >> 3) & 127, c = gi & 7;
        cp16(xs_a + (uint32_t)((kt * 128 + r) * AP + c * 4) * 4,
             X + (size_t)(m0 + r) * 128 + kt * 32 + c * 4);
    }
    cp_commit();

    // split W once: thread handles o = tid>>1, f in [(tid&1)*64, +64)
    {
        const int o = tid >> 1, fh = (tid & 1) * 64;
        const float4* wsrc = (const float4*)(W + o * 128 + fh);
#pragma unroll
        for (int j4 = 0; j4 < 16; j4++) {
            float4 w = wsrc[j4];
            float wv[4] = {w.x, w.y, w.z, w.w};
#pragma unroll
            for (int e = 0; e < 4; e++) {
                int f = fh + j4 * 4 + e;
                uint32_t h = tf32_rna(wv[e]);
                Whs[f * WS + o] = __uint_as_float(h);
                Wls[f * WS + o] = wv[e] - __uint_as_float(h);
            }
        }
    }
    cp_wait<0>();
    __syncthreads();

    float acc[2][8][4];
#pragma unroll
    for (int mi = 0; mi < 2; mi++)
#pragma unroll
        for (int ni = 0; ni < 8; ni++)
#pragma unroll
            for (int q = 0; q < 4; q++) acc[mi][ni][q] = 0.0f;

#pragma unroll
    for (int kt = 0; kt < 4; kt++) {
        const float* Xb = Xs + kt * 128 * AP;
#pragma unroll
        for (int k0 = 0; k0 < 32; k0 += 8) {
            uint32_t ah[2][4], al[2][4];
#pragma unroll
            for (int mi = 0; mi < 2; mi++) {
                int row = wr * 32 + mi * 16 + g;
#pragma unroll
                for (int q = 0; q < 4; q++) {
                    int rr = row + (q & 1) * 8, cc = k0 + tig + (q >> 1) * 4;
                    float x = Xb[rr * AP + cc];
                    uint32_t h = tf32_rna(x);
                    ah[mi][q] = h;
                    al[mi][q] = __float_as_uint(x - __uint_as_float(h));
                }
            }
            const int kbase = (kt * 32 + k0 + tig) * WS;
#pragma unroll
            for (int ni = 0; ni < 8; ni++) {
                int o = wc * 64 + ni * 8 + g;
                uint32_t bh[2], bl[2];
                bh[0] = __float_as_uint(Whs[kbase + o]);
                bh[1] = __float_as_uint(Whs[kbase + 4 * WS + o]);
                bl[0] = __float_as_uint(Wls[kbase + o]);
                bl[1] = __float_as_uint(Wls[kbase + 4 * WS + o]);
#pragma unroll
                for (int mi = 0; mi < 2; mi++) {
                    mma8(acc[mi][ni], ah[mi], bh);
                    mma8(acc[mi][ni], ah[mi], bl);
                    mma8(acc[mi][ni], al[mi], bh);
                }
            }
        }
    }
    __syncthreads();

    // ---- stage accumulators into packed-fragment order (C-frag: q>>1 = row+8,
    // q&1 = col+1). stage=wr, k = mi*16 + (q>>1)*8 + g, o = wc*64+ni*8+tig*2+(q&1)
#pragma unroll
    for (int mi = 0; mi < 2; mi++)
#pragma unroll
        for (int ni = 0; ni < 8; ni++)
#pragma unroll
            for (int q = 0; q < 4; q++) {
                int wc_m = wc * 2 + (ni >> 2);
                int chunk = wc_m * 64 + mi * 32 + (tig * 2 + (q & 1)) * 4 + (g & 3);
                int fic = (q >> 1) * 8 + (ni & 3) * 2 + ((g >> 2) & 1);
                sm[wr * 4096 + chunk * 16 + fic] = acc[mi][ni][q];
            }
    __syncthreads();

    const float4* s4 = (const float4*)sm;
    float4* dst = (float4*)(g_xw + (size_t)(blockIdx.x >> 3) * 131072 +
                            (size_t)(blockIdx.x & 7) * 16384);
#pragma unroll
    for (int i = 0; i < 16; i++) dst[tid + i * 256] = s4[tid + i * 256];
}

// =====================================================================
// k_main: per batch C = A @ XW, BM=64; grid (16,32), 256 thr, 3 CTAs/SM.
// warps: wr = wid&1 (32 rows), wc = wid>>1 (32 cols). Warp tile 32x32.
// smem: As[2][64][36] (18432B) | Bs 2*20480 | degs[64]
// =====================================================================
#define AS_BYTES (2 * 64 * AP * 4)
#define BS_BYTES (2 * 256 * 80)
#define MAIN_SMEM (AS_BYTES + BS_BYTES + 256)

__global__ __launch_bounds__(256, 3) void k_main(const float* __restrict__ A,
                                                 const float* __restrict__ bias,
                                                 float* __restrict__ out) {
    extern __shared__ float sm[];
    float* As = sm;
    char* smc = (char*)sm;
    float* degs = (float*)(smc + AS_BYTES + BS_BYTES);
    const uint32_t as_a = su32(As), bs_a = su32(smc + AS_BYTES);

    const int tid = threadIdx.x, lane = tid & 31, wid = tid >> 5;
    const int g = lane >> 2, tig = lane & 3;
    const int wr = wid & 1, wc = wid >> 1;
    const int m0 = blockIdx.x * 64, bz = blockIdx.y;
    const float* Ab = A + (size_t)bz * 1024 * 1024;
    const float* Bp = g_xw + (size_t)bz * 131072;  // packed

    auto loadT = [&](int buf, int s) {
#pragma unroll
        for (int i = 0; i < 2; i++) {
            int gi = tid + i * 256;           // 0..511
            int r = gi >> 3, c = gi & 7;
            cp16(as_a + (uint32_t)((buf * 64 + r) * AP + c * 4) * 4,
                 Ab + (size_t)(m0 + r) * 1024 + s * 32 + c * 4);
        }
        const float* src = Bp + s * 4096;
#pragma unroll
        for (int i = 0; i < 4; i++) {
            int gi = tid + i * 256;           // 0..1023 granules of 16B
            cp16(bs_a + (uint32_t)(buf * 20480 + (gi >> 2) * 80 + (gi & 3) * 16),
                 src + gi * 4);
        }
        cp_commit();
    };

    float acc[2][4][4];
#pragma unroll
    for (int mi = 0; mi < 2; mi++)
#pragma unroll
        for (int ni = 0; ni < 4; ni++)
#pragma unroll
            for (int q = 0; q < 4; q++) acc[mi][ni][q] = 0.0f;
    float dg[2][2] = {{0.0f, 0.0f}, {0.0f, 0.0f}};

    loadT(0, 0);

    for (int s = 0; s < 32; s++) {
        if (s < 31) { loadT((s + 1) & 1, s + 1); cp_wait<1>(); }
        else cp_wait<0>();
        __syncthreads();
        const int buf = s & 1;
        const char* bbase = smc + AS_BYTES + buf * 20480 + (wc * 64 + lane) * 80;
#pragma unroll
        for (int k0 = 0; k0 < 32; k0 += 8) {
            uint32_t a[2][4];
#pragma unroll
            for (int mi = 0; mi < 2; mi++) {
                int row = wr * 32 + mi * 16 + g;
#pragma unroll
                for (int q = 0; q < 4; q++) {
                    int rr = row + (q & 1) * 8, cc = k0 + tig + (q >> 1) * 4;
                    a[mi][q] = __float_as_uint(As[(buf * 64 + rr) * AP + cc]);
                }
            }
            // B: 8 floats = 2x LDS.128 (conflict-free, 80B lane stride)
            const float4* bb = (const float4*)(bbase + ((k0 >> 4) & 1) * 2560 +
                                               ((k0 >> 3) & 1) * 32);
            float4 v0 = bb[0], v1 = bb[1];
            float bf[8] = {v0.x, v0.y, v0.z, v0.w, v1.x, v1.y, v1.z, v1.w};
#pragma unroll
            for (int ni = 0; ni < 4; ni++) {
                uint32_t b[2] = {__float_as_uint(bf[ni * 2]),
                                 __float_as_uint(bf[ni * 2 + 1])};
                mma8(acc[0][ni], a[0], b);
                mma8(acc[1][ni], a[1], b);
            }
            if (wc == 0) {  // degree on the idle fma pipe
#pragma unroll
                for (int mi = 0; mi < 2; mi++) {
                    dg[mi][0] += __uint_as_float(a[mi][0]) + __uint_as_float(a[mi][2]);
                    dg[mi][1] += __uint_as_float(a[mi][1]) + __uint_as_float(a[mi][3]);
                }
            }
        }
        __syncthreads();
    }

    if (wc == 0) {  // reduce deg over the tig quad
#pragma unroll
        for (int mi = 0; mi < 2; mi++)
#pragma unroll
            for (int r = 0; r < 2; r++) {
                float v = dg[mi][r];
                v += __shfl_xor_sync(0xffffffffu, v, 1);
                v += __shfl_xor_sync(0xffffffffu, v, 2);
                if (tig == 0) degs[wr * 32 + mi * 16 + r * 8 + g] = v;
            }
    }
    __syncthreads();

    float inv[2][2];
#pragma unroll
    for (int mi = 0; mi < 2; mi++) {
        inv[mi][0] = 1.0f / degs[wr * 32 + mi * 16 + g];
        inv[mi][1] = 1.0f / degs[wr * 32 + mi * 16 + g + 8];
    }

#pragma unroll
    for (int ni = 0; ni < 4; ni++) {
        int col = wc * 32 + ni * 8 + tig * 2;
        float2 bv = *(const float2*)(bias + col);
#pragma unroll
        for (int mi = 0; mi < 2; mi++) {
            int row = m0 + wr * 32 + mi * 16 + g;
            float2 v0, v1;
            v0.x = leaky(fmaf(acc[mi][ni][0], inv[mi][0], bv.x));
            v0.y = leaky(fmaf(acc[mi][ni][1], inv[mi][0], bv.y));
            v1.x = leaky(fmaf(acc[mi][ni][2], inv[mi][1], bv.x));
            v1.y = leaky(fmaf(acc[mi][ni][3], inv[mi][1], bv.y));
            *(float2*)(out + ((size_t)bz * 1024 + row) * 128 + col) = v0;
            *(float2*)(out + ((size_t)bz * 1024 + row + 8) * 128 + col) = v1;
        }
    }
}

// ---------------- host ----------------
extern "C" void kernel_launch(void* const* d_in, const int* in_sizes, int n_in,
                              void* d_out, int out_size) {
    const float* X    = (const float*)d_in[0];  // [32,1024,128]
    const float* adj  = (const float*)d_in[1];  // [32,1024,1024]
    const float* W    = (const float*)d_in[2];  // [128,128]
    const float* bias = (const float*)d_in[3];  // [128]
    float* out = (float*)d_out;                 // [32,1024,128]

    static int inited = 0;
    if (!inited) {
        cudaFuncSetAttribute(k_xw, cudaFuncAttributeMaxDynamicSharedMemorySize, XW_SMEM);
        cudaFuncSetAttribute(k_main, cudaFuncAttributeMaxDynamicSharedMemorySize, MAIN_SMEM);
        inited = 1;
    }

    k_xw<<<256, 256, XW_SMEM>>>(X, W);
    k_main<<<dim3(16, 32), 256, MAIN_SMEM>>>(adj, bias, out);
}

// round 7
// speedup vs baseline: 1.2934x; 1.2934x over previous
#include <cuda_runtime.h>
#include <cstdint>

// out = LeakyReLU( D^-1 * (A @ (X @ W^T)) + b ),  B=32, N=1024, F=128
// Base-ISA tensor path (mma.sync m16n8k8 tf32 + cp.async).
//
// k_xw  : XW = X @ W^T, single tf32 pass (cvt.rna both operands). Output in
//         k_main's per-thread fragment order -> k_main B loads are LDS.128.
// k_main: C = A @ XW per batch (BM=128, occ 2); deg = rowsum(A) via FADD on
//         the idle fma pipe; epilogue leaky(C/deg + bias).

#define NEG_SLOPE 0.01f

__device__ float g_xw[32u * 1024u * 128u];  // packed-fragment XW (16 MB)

// ---------------- helpers ----------------
__device__ __forceinline__ uint32_t su32(const void* p) {
    uint32_t r;
    asm("{\n\t.reg .u64 t;\n\tcvta.to.shared.u64 t, %1;\n\tcvt.u32.u64 %0, t;\n\t}"
        : "=r"(r) : "l"(p));
    return r;
}
__device__ __forceinline__ void cp16(uint32_t dst, const void* src) {
    asm volatile("cp.async.cg.shared.global [%0], [%1], 16;" :: "r"(dst), "l"(src));
}
__device__ __forceinline__ void cp_commit() {
    asm volatile("cp.async.commit_group;" ::: "memory");
}
template <int N>
__device__ __forceinline__ void cp_wait() {
    asm volatile("cp.async.wait_group %0;" :: "n"(N) : "memory");
}
__device__ __forceinline__ uint32_t tf32_rna(float x) {
    uint32_t r;
    asm("cvt.rna.tf32.f32 %0, %1;" : "=r"(r) : "f"(x));
    return r;
}
__device__ __forceinline__ void mma8(float* c, const uint32_t* a, const uint32_t* b) {
    asm volatile(
        "mma.sync.aligned.m16n8k8.row.col.f32.tf32.tf32.f32 "
        "{%0,%1,%2,%3}, {%4,%5,%6,%7}, {%8,%9}, {%0,%1,%2,%3};"
        : "+f"(c[0]), "+f"(c[1]), "+f"(c[2]), "+f"(c[3])
        : "r"(a[0]), "r"(a[1]), "r"(a[2]), "r"(a[3]), "r"(b[0]), "r"(b[1]));
}
__device__ __forceinline__ float leaky(float v) {
    return (v >= 0.0f) ? v : NEG_SLOPE * v;
}

#define AP 36   // A/X smem row pad (floats): frag LDS bank = 4g+tig (bijective)
#define BP 132  // W smem row pad: bank = (4*(o&7) + k&31...) -> conflict-free

// =====================================================================
// k_xw: XW = X @ W^T.  grid=256 (m-tiles of 128), 256 threads, occ 2.
// smem: Ws[128][BP] (W[o][f], tf32-converted in place) | Xs[2][128][AP].
// Staging reuses sm[0..16384) after the main loop.
// Packed layout == R5's (verified): per CTA region 16384 floats at
//   g_xw + batch*131072 + (bx&7)*16384, idx =
//   (((wr*2+wc)*4 + mi*2 + (q>>1))*32 + (tig*2+(q&1))*4 + (g&3))*16
//   + ni*2 + ((g>>2)&1)
// =====================================================================
#define XW_SMEM ((128 * BP + 2 * 128 * AP) * 4)

__global__ __launch_bounds__(256, 2) void k_xw(const float* __restrict__ X,
                                               const float* __restrict__ W) {
    extern __shared__ float sm[];
    float* Ws = sm;                 // 128*BP floats
    float* Xs = sm + 128 * BP;      // 2*128*AP floats
    const uint32_t ws_a = su32(Ws), xs_a = su32(Xs);

    const int tid = threadIdx.x, lane = tid & 31, wid = tid >> 5;
    const int g = lane >> 2, tig = lane & 3;
    const int wr = wid & 3, wc = wid >> 2;
    const int m0 = blockIdx.x * 128;

    // group A: whole W [128][128] -> Ws[o][f]
#pragma unroll
    for (int i = 0; i < 16; i++) {
        int idx = tid + i * 256;
        int o = idx >> 5, f4 = idx & 31;
        cp16(ws_a + (uint32_t)(o * BP + f4 * 4) * 4, W + o * 128 + f4 * 4);
    }
    cp_commit();

    const int lr = tid >> 3, lc4 = tid & 7;
    auto loadX = [&](int buf, int kt) {
#pragma unroll
        for (int i = 0; i < 4; i++) {
            int row = lr + i * 32;
            cp16(xs_a + (uint32_t)((buf * 128 + row) * AP + lc4 * 4) * 4,
                 X + (size_t)(m0 + row) * 128 + kt * 32 + lc4 * 4);
        }
        cp_commit();
    };
    loadX(0, 0);  // group B

    // convert W to tf32 in place (once). W group done after wait<1>.
    cp_wait<1>();
    __syncthreads();
#pragma unroll 8
    for (int i = 0; i < 64; i++) {
        int idx = tid + i * 256;          // 0..16383
        int o = idx >> 7, f = idx & 127;
        float* p = Ws + o * BP + f;
        *p = __uint_as_float(tf32_rna(*p));
    }
    __syncthreads();

    float acc[2][8][4];
#pragma unroll
    for (int mi = 0; mi < 2; mi++)
#pragma unroll
        for (int ni = 0; ni < 8; ni++)
#pragma unroll
            for (int q = 0; q < 4; q++) acc[mi][ni][q] = 0.0f;

    for (int kt = 0; kt < 4; kt++) {
        if (kt < 3) { loadX((kt + 1) & 1, kt + 1); cp_wait<1>(); }
        else cp_wait<0>();
        __syncthreads();
        const int buf = kt & 1;
#pragma unroll
        for (int k0 = 0; k0 < 32; k0 += 8) {
            uint32_t a[2][4];
#pragma unroll
            for (int mi = 0; mi < 2; mi++) {
                int row = wr * 32 + mi * 16 + g;
#pragma unroll
                for (int q = 0; q < 4; q++) {
                    int rr = row + (q & 1) * 8, cc = k0 + tig + (q >> 1) * 4;
                    a[mi][q] = tf32_rna(Xs[(buf * 128 + rr) * AP + cc]);
                }
            }
#pragma unroll
            for (int ni = 0; ni < 8; ni++) {
                int o = wc * 64 + ni * 8 + g;
                uint32_t b[2];
                b[0] = __float_as_uint(Ws[o * BP + kt * 32 + k0 + tig]);
                b[1] = __float_as_uint(Ws[o * BP + kt * 32 + k0 + tig + 4]);
                mma8(acc[0][ni], a[0], b);
                mma8(acc[1][ni], a[1], b);
            }
        }
        __syncthreads();
    }

    // ---- stage accumulators into packed-fragment order (C-frag: q>>1=row+8,
    // q&1=col+1) ----
#pragma unroll
    for (int mi = 0; mi < 2; mi++)
#pragma unroll
        for (int ni = 0; ni < 8; ni++)
#pragma unroll
            for (int q = 0; q < 4; q++) {
                int qr = q >> 1;
                int qc = q & 1;
                int idx = ((((wr * 2 + wc) * 4 + mi * 2 + qr) * 32) +
                           (tig * 2 + qc) * 4 + (g & 3)) * 16 +
                          ni * 2 + ((g >> 2) & 1);
                sm[idx] = acc[mi][ni][q];
            }
    __syncthreads();

    const float4* s4 = (const float4*)sm;
    float4* dst = (float4*)(g_xw + (size_t)(blockIdx.x >> 3) * 131072 +
                            (size_t)(blockIdx.x & 7) * 16384);
#pragma unroll
    for (int i = 0; i < 16; i++) dst[tid + i * 256] = s4[tid + i * 256];
}

// =====================================================================
// k_main: per batch C = A[1024,1024] @ XW; deg fused as FADD; grid (8,32).
// smem bytes: As 2*128*AP*4 = 36864 | Bs 2*256*80 = 40960 | degs 512
// B stage layout: 256 blocks of 64B data at 80B stride (conflict-free LDS.128)
// =====================================================================
#define AS_BYTES (2 * 128 * AP * 4)
#define BS_BYTES (2 * 256 * 80)
#define MAIN_SMEM (AS_BYTES + BS_BYTES + 512)

__global__ __launch_bounds__(256, 2) void k_main(const float* __restrict__ A,
                                                 const float* __restrict__ bias,
                                                 float* __restrict__ out) {
    extern __shared__ float sm[];
    float* As = sm;
    char* smc = (char*)sm;
    float* degs = (float*)(smc + AS_BYTES + BS_BYTES);
    const uint32_t as_a = su32(As), bs_a = su32(smc + AS_BYTES);

    const int tid = threadIdx.x, lane = tid & 31, wid = tid >> 5;
    const int g = lane >> 2, tig = lane & 3;
    const int wr = wid & 3, wc = wid >> 2;
    const int m0 = blockIdx.x * 128, bz = blockIdx.y;
    const float* Ab = A + (size_t)bz * 1024 * 1024;
    const float* Bp = g_xw + (size_t)bz * 131072;  // packed

    const int lr = tid >> 3, lc4 = tid & 7;  // A: 128 rows x 8 f4

    auto loadT = [&](int buf, int s) {
#pragma unroll
        for (int i = 0; i < 4; i++) {
            int row = lr + i * 32;
            cp16(as_a + (uint32_t)((buf * 128 + row) * AP + lc4 * 4) * 4,
                 Ab + (size_t)(m0 + row) * 1024 + s * 32 + lc4 * 4);
        }
        // B: 1024 chunks of 16B; gmem dense, smem 64B-blocks at 80B stride
        const float* src = Bp + s * 4096;
#pragma unroll
        for (int i = 0; i < 4; i++) {
            int chunk = tid + i * 256;
            cp16(bs_a + (uint32_t)(buf * 20480 + (chunk >> 2) * 80 + (chunk & 3) * 16),
                 src + chunk * 4);
        }
        cp_commit();
    };

    float acc[2][8][4];
#pragma unroll
    for (int mi = 0; mi < 2; mi++)
#pragma unroll
        for (int ni = 0; ni < 8; ni++)
#pragma unroll
            for (int q = 0; q < 4; q++) acc[mi][ni][q] = 0.0f;
    float dg[2][2] = {{0.0f, 0.0f}, {0.0f, 0.0f}};

    loadT(0, 0);

    for (int s = 0; s < 32; s++) {
        if (s < 31) { loadT((s + 1) & 1, s + 1); cp_wait<1>(); }
        else cp_wait<0>();
        __syncthreads();
        const int buf = s & 1;
#pragma unroll
        for (int k0 = 0; k0 < 32; k0 += 8) {
            uint32_t a[2][4];
#pragma unroll
            for (int mi = 0; mi < 2; mi++) {
                int row = wr * 32 + mi * 16 + g;
#pragma unroll
                for (int q = 0; q < 4; q++) {
                    int rr = row + (q & 1) * 8, cc = k0 + tig + (q >> 1) * 4;
                    a[mi][q] = __float_as_uint(As[(buf * 128 + rr) * AP + cc]);
                }
            }
            // B fragments: 4x LDS.128, conflict-free (80B lane stride)
            const float4* bb = (const float4*)(smc + AS_BYTES + buf * 20480 +
                                               ((wc * 4 + (k0 >> 3)) * 32 + lane) * 80);
            float4 bqv[4];
#pragma unroll
            for (int j = 0; j < 4; j++) bqv[j] = bb[j];

#pragma unroll
            for (int ni = 0; ni < 8; ni++) {
                float4 qv = bqv[ni >> 1];
                float b0f = (ni & 1) ? qv.z : qv.x;
                float b1f = (ni & 1) ? qv.w : qv.y;
                uint32_t b[2] = {__float_as_uint(b0f), __float_as_uint(b1f)};
                mma8(acc[0][ni], a[0], b);
                mma8(acc[1][ni], a[1], b);
            }
            if (wc == 0) {  // degree on the idle fma pipe
#pragma unroll
                for (int mi = 0; mi < 2; mi++) {
                    dg[mi][0] += __uint_as_float(a[mi][0]) + __uint_as_float(a[mi][2]);
                    dg[mi][1] += __uint_as_float(a[mi][1]) + __uint_as_float(a[mi][3]);
                }
            }
        }
        __syncthreads();
    }

    if (wc == 0) {  // reduce deg over the tig quad (lane bits 0-1)
#pragma unroll
        for (int mi = 0; mi < 2; mi++)
#pragma unroll
            for (int r = 0; r < 2; r++) {
                float v = dg[mi][r];
                v += __shfl_xor_sync(0xffffffffu, v, 1);
                v += __shfl_xor_sync(0xffffffffu, v, 2);
                if (tig == 0) degs[wr * 32 + mi * 16 + r * 8 + g] = v;
            }
    }
    __syncthreads();

    float inv[2][2];
#pragma unroll
    for (int mi = 0; mi < 2; mi++) {
        inv[mi][0] = 1.0f / degs[wr * 32 + mi * 16 + g];
        inv[mi][1] = 1.0f / degs[wr * 32 + mi * 16 + g + 8];
    }

#pragma unroll
    for (int ni = 0; ni < 8; ni++) {
        int col = wc * 64 + ni * 8 + tig * 2;
        float2 bv = *(const float2*)(bias + col);
#pragma unroll
        for (int mi = 0; mi < 2; mi++) {
            int row = m0 + wr * 32 + mi * 16 + g;
            float2 v0, v1;
            v0.x = leaky(fmaf(acc[mi][ni][0], inv[mi][0], bv.x));
            v0.y = leaky(fmaf(acc[mi][ni][1], inv[mi][0], bv.y));
            v1.x = leaky(fmaf(acc[mi][ni][2], inv[mi][1], bv.x));
            v1.y = leaky(fmaf(acc[mi][ni][3], inv[mi][1], bv.y));
            *(float2*)(out + ((size_t)bz * 1024 + row) * 128 + col) = v0;
            *(float2*)(out + ((size_t)bz * 1024 + row + 8) * 128 + col) = v1;
        }
    }
}

// ---------------- host ----------------
extern "C" void kernel_launch(void* const* d_in, const int* in_sizes, int n_in,
                              void* d_out, int out_size) {
    const float* X    = (const float*)d_in[0];  // [32,1024,128]
    const float* adj  = (const float*)d_in[1];  // [32,1024,1024]
    const float* W    = (const float*)d_in[2];  // [128,128]
    const float* bias = (const float*)d_in[3];  // [128]
    float* out = (float*)d_out;                 // [32,1024,128]

    static int inited = 0;
    if (!inited) {
        cudaFuncSetAttribute(k_xw, cudaFuncAttributeMaxDynamicSharedMemorySize, XW_SMEM);
        cudaFuncSetAttribute(k_main, cudaFuncAttributeMaxDynamicSharedMemorySize, MAIN_SMEM);
        inited = 1;
    }

    k_xw<<<256, 256, XW_SMEM>>>(X, W);
    k_main<<<dim3(8, 32), 256, MAIN_SMEM>>>(adj, bias, out);
}

// round 8
// speedup vs baseline: 1.7173x; 1.3277x over previous
#include <cuda_runtime.h>
#include <cuda_fp16.h>
#include <cstdint>

// out = LeakyReLU( D^-1 * (A @ (X @ W^T)) + b ),  B=32, N=1024, F=128
//
// k_xw  : XW = X @ W^T via tf32 mma (single pass), output fp16 [m][o].
// k_main: C = A @ XW per batch via fp16 m16n8k16 mma. A kept fp32 in smem
//         (cp.async), frags cvt'd to fp16 in regs; deg = rowsum(A) from the
//         fp32 values (FADD, idle fma pipe). B frags via ldmatrix.x4.trans.
//         Epilogue: leaky(C/deg + bias), all fp32.

#define NEG_SLOPE 0.01f

__device__ __half g_xw[32u * 1024u * 128u];  // fp16 XW (8 MB)

// ---------------- helpers ----------------
__device__ __forceinline__ uint32_t su32(const void* p) {
    uint32_t r;
    asm("{\n\t.reg .u64 t;\n\tcvta.to.shared.u64 t, %1;\n\tcvt.u32.u64 %0, t;\n\t}"
        : "=r"(r) : "l"(p));
    return r;
}
__device__ __forceinline__ void cp16(uint32_t dst, const void* src) {
    asm volatile("cp.async.cg.shared.global [%0], [%1], 16;" :: "r"(dst), "l"(src));
}
__device__ __forceinline__ void cp_commit() {
    asm volatile("cp.async.commit_group;" ::: "memory");
}
template <int N>
__device__ __forceinline__ void cp_wait() {
    asm volatile("cp.async.wait_group %0;" :: "n"(N) : "memory");
}
__device__ __forceinline__ uint32_t tf32_rna(float x) {
    uint32_t r;
    asm("cvt.rna.tf32.f32 %0, %1;" : "=r"(r) : "f"(x));
    return r;
}
__device__ __forceinline__ void mma_tf32(float* c, const uint32_t* a, const uint32_t* b) {
    asm volatile(
        "mma.sync.aligned.m16n8k8.row.col.f32.tf32.tf32.f32 "
        "{%0,%1,%2,%3}, {%4,%5,%6,%7}, {%8,%9}, {%0,%1,%2,%3};"
        : "+f"(c[0]), "+f"(c[1]), "+f"(c[2]), "+f"(c[3])
        : "r"(a[0]), "r"(a[1]), "r"(a[2]), "r"(a[3]), "r"(b[0]), "r"(b[1]));
}
__device__ __forceinline__ void mma_f16(float* c, const uint32_t* a, const uint32_t* b) {
    asm volatile(
        "mma.sync.aligned.m16n8k16.row.col.f32.f16.f16.f32 "
        "{%0,%1,%2,%3}, {%4,%5,%6,%7}, {%8,%9}, {%0,%1,%2,%3};"
        : "+f"(c[0]), "+f"(c[1]), "+f"(c[2]), "+f"(c[3])
        : "r"(a[0]), "r"(a[1]), "r"(a[2]), "r"(a[3]), "r"(b[0]), "r"(b[1]));
}
__device__ __forceinline__ void ldmat4t(uint32_t* r, uint32_t addr) {
    asm volatile(
        "ldmatrix.sync.aligned.m8n8.x4.trans.shared.b16 {%0,%1,%2,%3}, [%4];"
        : "=r"(r[0]), "=r"(r[1]), "=r"(r[2]), "=r"(r[3]) : "r"(addr));
}
__device__ __forceinline__ uint32_t pack_h2(float lo, float hi) {
    uint32_t r;
    asm("cvt.rn.f16x2.f32 %0, %2, %1;" : "=r"(r) : "f"(lo), "f"(hi));
    return r;
}
__device__ __forceinline__ float leaky(float v) {
    return (v >= 0.0f) ? v : NEG_SLOPE * v;
}

#define XAP 36  // k_xw X pad (R7 proven)
#define BP 132  // k_xw W pad (R7 proven)
#define AP 40   // k_main A pad: LDS.64 frag pairs conflict-free per half-warp

// =====================================================================
// k_xw: XW = X @ W^T (tf32, single pass).  grid=256, 256 threads, occ 2.
// Identical to R7 except the epilogue stores fp16 [m][o] directly.
// =====================================================================
#define XW_SMEM ((128 * BP + 2 * 128 * XAP) * 4)

__global__ __launch_bounds__(256, 2) void k_xw(const float* __restrict__ X,
                                               const float* __restrict__ W) {
    extern __shared__ float sm[];
    float* Ws = sm;
    float* Xs = sm + 128 * BP;
    const uint32_t ws_a = su32(Ws), xs_a = su32(Xs);

    const int tid = threadIdx.x, lane = tid & 31, wid = tid >> 5;
    const int g = lane >> 2, tig = lane & 3;
    const int wr = wid & 3, wc = wid >> 2;
    const int m0 = blockIdx.x * 128;

#pragma unroll
    for (int i = 0; i < 16; i++) {
        int idx = tid + i * 256;
        int o = idx >> 5, f4 = idx & 31;
        cp16(ws_a + (uint32_t)(o * BP + f4 * 4) * 4, W + o * 128 + f4 * 4);
    }
    cp_commit();

    const int lr = tid >> 3, lc4 = tid & 7;
    auto loadX = [&](int buf, int kt) {
#pragma unroll
        for (int i = 0; i < 4; i++) {
            int row = lr + i * 32;
            cp16(xs_a + (uint32_t)((buf * 128 + row) * XAP + lc4 * 4) * 4,
                 X + (size_t)(m0 + row) * 128 + kt * 32 + lc4 * 4);
        }
        cp_commit();
    };
    loadX(0, 0);

    cp_wait<1>();
    __syncthreads();
#pragma unroll 8
    for (int i = 0; i < 64; i++) {
        int idx = tid + i * 256;
        int o = idx >> 7, f = idx & 127;
        float* p = Ws + o * BP + f;
        *p = __uint_as_float(tf32_rna(*p));
    }
    __syncthreads();

    float acc[2][8][4];
#pragma unroll
    for (int mi = 0; mi < 2; mi++)
#pragma unroll
        for (int ni = 0; ni < 8; ni++)
#pragma unroll
            for (int q = 0; q < 4; q++) acc[mi][ni][q] = 0.0f;

    for (int kt = 0; kt < 4; kt++) {
        if (kt < 3) { loadX((kt + 1) & 1, kt + 1); cp_wait<1>(); }
        else cp_wait<0>();
        __syncthreads();
        const int buf = kt & 1;
#pragma unroll
        for (int k0 = 0; k0 < 32; k0 += 8) {
            uint32_t a[2][4];
#pragma unroll
            for (int mi = 0; mi < 2; mi++) {
                int row = wr * 32 + mi * 16 + g;
#pragma unroll
                for (int q = 0; q < 4; q++) {
                    int rr = row + (q & 1) * 8, cc = k0 + tig + (q >> 1) * 4;
                    a[mi][q] = tf32_rna(Xs[(buf * 128 + rr) * XAP + cc]);
                }
            }
#pragma unroll
            for (int ni = 0; ni < 8; ni++) {
                int o = wc * 64 + ni * 8 + g;
                uint32_t b[2];
                b[0] = __float_as_uint(Ws[o * BP + kt * 32 + k0 + tig]);
                b[1] = __float_as_uint(Ws[o * BP + kt * 32 + k0 + tig + 4]);
                mma_tf32(acc[0][ni], a[0], b);
                mma_tf32(acc[1][ni], a[1], b);
            }
        }
        __syncthreads();
    }

    // epilogue: pack adjacent-column pairs (c0,c1)/(c2,c3) as half2, store fp16
    uint32_t* outp = (uint32_t*)g_xw;
#pragma unroll
    for (int mi = 0; mi < 2; mi++) {
        int row = m0 + wr * 32 + mi * 16 + g;
#pragma unroll
        for (int ni = 0; ni < 8; ni++) {
            int col2 = wc * 32 + ni * 4 + tig;  // half2 index within row (64)
            outp[(size_t)row * 64 + col2] = pack_h2(acc[mi][ni][0], acc[mi][ni][1]);
            outp[(size_t)(row + 8) * 64 + col2] = pack_h2(acc[mi][ni][2], acc[mi][ni][3]);
        }
    }
}

// =====================================================================
// k_main: per batch C = A @ XW (fp16 mma); grid (8,32), 256 threads.
// smem: As[2][128][AP] fp32 (40960B) | Bs[2][32][136] fp16 (17408B) | degs
// =====================================================================
#define AS_BYTES (2 * 128 * AP * 4)
#define BS_BYTES (2 * 32 * 136 * 2)
#define BSTRIDE 8704  // 32*136*2
#define MAIN_SMEM (AS_BYTES + BS_BYTES + 512)

__global__ __launch_bounds__(256, 2) void k_main(const float* __restrict__ A,
                                                 const float* __restrict__ bias,
                                                 float* __restrict__ out) {
    extern __shared__ float sm[];
    char* smc = (char*)sm;
    const float2* As2 = (const float2*)sm;
    float* degs = (float*)(smc + AS_BYTES + BS_BYTES);
    const uint32_t as_a = su32(sm), bs_a = su32(smc + AS_BYTES);

    const int tid = threadIdx.x, lane = tid & 31, wid = tid >> 5;
    const int g = lane >> 2, tig = lane & 3;
    const int wr = wid & 3, wc = wid >> 2;
    const int m0 = blockIdx.x * 128, bz = blockIdx.y;
    const float* Ab = A + (size_t)bz * 1024 * 1024;
    const __half* Bp = g_xw + (size_t)bz * 131072;

    const int lr = tid >> 3, lc4 = tid & 7;

    auto loadT = [&](int buf, int s) {
#pragma unroll
        for (int i = 0; i < 4; i++) {
            int row = lr + i * 32;
            cp16(as_a + (uint32_t)((buf * 128 + row) * AP + lc4 * 4) * 4,
                 Ab + (size_t)(m0 + row) * 1024 + s * 32 + lc4 * 4);
        }
        // B: 32 rows x 128 halves -> [k][136] halves; 512 granules of 16B
        const char* src = (const char*)(Bp + s * 32 * 128);
#pragma unroll
        for (int i = 0; i < 2; i++) {
            int gi = tid + i * 256;
            int r = gi >> 4, c = gi & 15;
            cp16(bs_a + (uint32_t)(buf * BSTRIDE + r * 272 + c * 16),
                 src + r * 256 + c * 16);
        }
        cp_commit();
    };

    float acc[2][8][4];
#pragma unroll
    for (int mi = 0; mi < 2; mi++)
#pragma unroll
        for (int ni = 0; ni < 8; ni++)
#pragma unroll
            for (int q = 0; q < 4; q++) acc[mi][ni][q] = 0.0f;
    float dg[2][2] = {{0.0f, 0.0f}, {0.0f, 0.0f}};

    loadT(0, 0);

    // ldmatrix lane address components (constant across stages):
    //   lanes 0-15 -> k-row (lane&15), lanes 16-31 -> n offset +8
    const int lm_k = lane & 15;
    const int lm_n8 = (lane >> 4) * 8;

    for (int s = 0; s < 32; s++) {
        if (s < 31) { loadT((s + 1) & 1, s + 1); cp_wait<1>(); }
        else cp_wait<0>();
        __syncthreads();
        const int buf = s & 1;
        const uint32_t bsb = bs_a + buf * BSTRIDE;

#pragma unroll
        for (int h = 0; h < 2; h++) {  // k16 halves of the k32 stage
            // ---- A fragments: fp32 pairs -> fp16x2 ----
            uint32_t a[2][4];
#pragma unroll
            for (int mi = 0; mi < 2; mi++) {
                int row = wr * 32 + mi * 16 + g;
                int base = (buf * 128 + row) * (AP / 2) + h * 8 + tig;
                float2 u0 = As2[base];                      // (g,   2tig)
                float2 u1 = As2[base + 8 * (AP / 2)];       // (g+8, 2tig)
                float2 u2 = As2[base + 4];                  // (g,   2tig+8)
                float2 u3 = As2[base + 8 * (AP / 2) + 4];   // (g+8, 2tig+8)
                a[mi][0] = pack_h2(u0.x, u0.y);
                a[mi][1] = pack_h2(u1.x, u1.y);
                a[mi][2] = pack_h2(u2.x, u2.y);
                a[mi][3] = pack_h2(u3.x, u3.y);
                if (wc == 0) {
                    dg[mi][0] += (u0.x + u0.y) + (u2.x + u2.y);
                    dg[mi][1] += (u1.x + u1.y) + (u3.x + u3.y);
                }
            }
            // ---- B fragments: 4x ldmatrix.x4.trans (k16 x n64) ----
            uint32_t bfr[4][4];
#pragma unroll
            for (int j = 0; j < 4; j++) {
                int n0 = wc * 64 + j * 16 + lm_n8;
                uint32_t addr = bsb + (uint32_t)((h * 16 + lm_k) * 272 + n0 * 2);
                ldmat4t(bfr[j], addr);
            }
#pragma unroll
            for (int ni = 0; ni < 8; ni++) {
                const uint32_t* b = &bfr[ni >> 1][(ni & 1) * 2];
                mma_f16(acc[0][ni], a[0], b);
                mma_f16(acc[1][ni], a[1], b);
            }
        }
        __syncthreads();
    }

    if (wc == 0) {
#pragma unroll
        for (int mi = 0; mi < 2; mi++)
#pragma unroll
            for (int r = 0; r < 2; r++) {
                float v = dg[mi][r];
                v += __shfl_xor_sync(0xffffffffu, v, 1);
                v += __shfl_xor_sync(0xffffffffu, v, 2);
                if (tig == 0) degs[wr * 32 + mi * 16 + r * 8 + g] = v;
            }
    }
    __syncthreads();

    float inv[2][2];
#pragma unroll
    for (int mi = 0; mi < 2; mi++) {
        inv[mi][0] = 1.0f / degs[wr * 32 + mi * 16 + g];
        inv[mi][1] = 1.0f / degs[wr * 32 + mi * 16 + g + 8];
    }

#pragma unroll
    for (int ni = 0; ni < 8; ni++) {
        int col = wc * 64 + ni * 8 + tig * 2;
        float2 bv = *(const float2*)(bias + col);
#pragma unroll
        for (int mi = 0; mi < 2; mi++) {
            int row = m0 + wr * 32 + mi * 16 + g;
            float2 v0, v1;
            v0.x = leaky(fmaf(acc[mi][ni][0], inv[mi][0], bv.x));
            v0.y = leaky(fmaf(acc[mi][ni][1], inv[mi][0], bv.y));
            v1.x = leaky(fmaf(acc[mi][ni][2], inv[mi][1], bv.x));
            v1.y = leaky(fmaf(acc[mi][ni][3], inv[mi][1], bv.y));
            *(float2*)(out + ((size_t)bz * 1024 + row) * 128 + col) = v0;
            *(float2*)(out + ((size_t)bz * 1024 + row + 8) * 128 + col) = v1;
        }
    }
}

// ---------------- host ----------------
extern "C" void kernel_launch(void* const* d_in, const int* in_sizes, int n_in,
                              void* d_out, int out_size) {
    const float* X    = (const float*)d_in[0];  // [32,1024,128]
    const float* adj  = (const float*)d_in[1];  // [32,1024,1024]
    const float* W    = (const float*)d_in[2];  // [128,128]
    const float* bias = (const float*)d_in[3];  // [128]
    float* out = (float*)d_out;                 // [32,1024,128]

    static int inited = 0;
    if (!inited) {
        cudaFuncSetAttribute(k_xw, cudaFuncAttributeMaxDynamicSharedMemorySize, XW_SMEM);
        cudaFuncSetAttribute(k_main, cudaFuncAttributeMaxDynamicSharedMemorySize, MAIN_SMEM);
        inited = 1;
    }

    k_xw<<<256, 256, XW_SMEM>>>(X, W);
    k_main<<<dim3(8, 32), 256, MAIN_SMEM>>>(adj, bias, out);
}

// round 9
// speedup vs baseline: 1.8315x; 1.0665x over previous
#include <cuda_runtime.h>
#include <cuda_fp16.h>
#include <cstdint>

// out = LeakyReLU( D^-1 * (A @ (X @ W^T)) + b ),  B=32, N=1024, F=128
//
// k_xw  : XW = X @ W^T via fp16 m16n8k16. W cvt'd once per CTA to resident
//         fp16 smem [f][o] (ldmatrix source); X via 3-deep cp.async ring.
//         Output fp16 [m][o].
// k_main: C = A @ XW per batch via fp16 m16n8k16, 3-stage cp.async pipeline.
//         A fp32 in smem, frags cvt'd in regs; deg = rowsum(A) in fp32 (FADD).
//         Epilogue: leaky(C/deg + bias), fp32.

#define NEG_SLOPE 0.01f

__device__ __half g_xw[32u * 1024u * 128u];  // fp16 XW (8 MB)

// ---------------- helpers ----------------
__device__ __forceinline__ uint32_t su32(const void* p) {
    uint32_t r;
    asm("{\n\t.reg .u64 t;\n\tcvta.to.shared.u64 t, %1;\n\tcvt.u32.u64 %0, t;\n\t}"
        : "=r"(r) : "l"(p));
    return r;
}
__device__ __forceinline__ void cp16(uint32_t dst, const void* src) {
    asm volatile("cp.async.cg.shared.global [%0], [%1], 16;" :: "r"(dst), "l"(src));
}
__device__ __forceinline__ void cp_commit() {
    asm volatile("cp.async.commit_group;" ::: "memory");
}
template <int N>
__device__ __forceinline__ void cp_wait() {
    asm volatile("cp.async.wait_group %0;" :: "n"(N) : "memory");
}
__device__ __forceinline__ void mma_f16(float* c, const uint32_t* a, const uint32_t* b) {
    asm volatile(
        "mma.sync.aligned.m16n8k16.row.col.f32.f16.f16.f32 "
        "{%0,%1,%2,%3}, {%4,%5,%6,%7}, {%8,%9}, {%0,%1,%2,%3};"
        : "+f"(c[0]), "+f"(c[1]), "+f"(c[2]), "+f"(c[3])
        : "r"(a[0]), "r"(a[1]), "r"(a[2]), "r"(a[3]), "r"(b[0]), "r"(b[1]));
}
__device__ __forceinline__ void ldmat4t(uint32_t* r, uint32_t addr) {
    asm volatile(
        "ldmatrix.sync.aligned.m8n8.x4.trans.shared.b16 {%0,%1,%2,%3}, [%4];"
        : "=r"(r[0]), "=r"(r[1]), "=r"(r[2]), "=r"(r[3]) : "r"(addr));
}
__device__ __forceinline__ uint32_t pack_h2(float lo, float hi) {
    uint32_t r;
    asm("cvt.rn.f16x2.f32 %0, %2, %1;" : "=r"(r) : "f"(lo), "f"(hi));
    return r;
}
__device__ __forceinline__ float leaky(float v) {
    return (v >= 0.0f) ? v : NEG_SLOPE * v;
}

#define AP 40  // fp32 A/X pad (floats): LDS.64 frag pairs conflict-free

// =====================================================================
// k_xw: XW = X @ W^T (fp16 mma). grid=512 (m-tiles of 64), 256 thr, occ 3.
// smem: Wh fp16 [128 f][136 o] (34816B) | Xs 3 x [64][40] fp32 (30720B)
// Warps: wr=wid&1 (32 rows), wc=wid>>1 (32 cols); warp tile 32x32.
// =====================================================================
#define XW_SMEM 65536

__global__ __launch_bounds__(256, 3) void k_xw(const float* __restrict__ X,
                                               const float* __restrict__ W) {
    extern __shared__ float sm[];
    char* smc = (char*)sm;
    __half* Wh = (__half*)sm;
    const uint32_t wh_a = su32(smc), xs_a = su32(smc + 34816);
    const float2* Xs2 = (const float2*)(smc + 34816);

    const int tid = threadIdx.x, lane = tid & 31, wid = tid >> 5;
    const int g = lane >> 2, tig = lane & 3;
    const int wr = wid & 1, wc = wid >> 1;
    const int m0 = blockIdx.x * 64;

    auto loadX = [&](int buf, int s) {
#pragma unroll
        for (int i = 0; i < 2; i++) {
            int gi = tid + i * 256;          // 0..511 float4 granules
            int r = gi >> 3, c = gi & 7;
            cp16(xs_a + (uint32_t)(buf * 10240 + r * 160 + c * 16),
                 X + (size_t)(m0 + r) * 128 + s * 32 + c * 4);
        }
        cp_commit();
    };
    loadX(0, 0);
    loadX(1, 1);

    // convert W -> Wh[f][o] once (o = tid>>1, 64 f each; LDG hits L2 hot)
    {
        const int o = tid >> 1, fh = (tid & 1) * 64;
        const float4* wsrc = (const float4*)(W + o * 128 + fh);
#pragma unroll
        for (int j4 = 0; j4 < 16; j4++) {
            float4 w = wsrc[j4];
            int f = fh + j4 * 4;
            Wh[(f + 0) * 136 + o] = __float2half_rn(w.x);
            Wh[(f + 1) * 136 + o] = __float2half_rn(w.y);
            Wh[(f + 2) * 136 + o] = __float2half_rn(w.z);
            Wh[(f + 3) * 136 + o] = __float2half_rn(w.w);
        }
    }

    float acc[2][4][4];
#pragma unroll
    for (int mi = 0; mi < 2; mi++)
#pragma unroll
        for (int ni = 0; ni < 4; ni++)
#pragma unroll
            for (int q = 0; q < 4; q++) acc[mi][ni][q] = 0.0f;

    const int lm_k = lane & 15;
    const int lm_n8 = (lane >> 4) * 8;

    int buf = 0;
    for (int s = 0; s < 4; s++) {
        if (s < 2) { loadX((s + 2) % 3, s + 2); cp_wait<2>(); }
        else if (s == 2) cp_wait<1>();
        else cp_wait<0>();
        __syncthreads();  // also covers the one-time W convert at s=0

#pragma unroll
        for (int h = 0; h < 2; h++) {
            uint32_t a[2][4];
#pragma unroll
            for (int mi = 0; mi < 2; mi++) {
                int row = wr * 32 + mi * 16 + g;
                int base = (buf * 64 + row) * (AP / 2) + h * 8 + tig;
                float2 u0 = Xs2[base];
                float2 u1 = Xs2[base + 8 * (AP / 2)];
                float2 u2 = Xs2[base + 4];
                float2 u3 = Xs2[base + 8 * (AP / 2) + 4];
                a[mi][0] = pack_h2(u0.x, u0.y);
                a[mi][1] = pack_h2(u1.x, u1.y);
                a[mi][2] = pack_h2(u2.x, u2.y);
                a[mi][3] = pack_h2(u3.x, u3.y);
            }
            uint32_t bfr[2][4];
#pragma unroll
            for (int j = 0; j < 2; j++) {
                int n0 = wc * 32 + j * 16 + lm_n8;
                uint32_t addr = wh_a +
                    (uint32_t)((s * 32 + h * 16 + lm_k) * 136 + n0) * 2;
                ldmat4t(bfr[j], addr);
            }
#pragma unroll
            for (int ni = 0; ni < 4; ni++) {
                const uint32_t* b = &bfr[ni >> 1][(ni & 1) * 2];
                mma_f16(acc[0][ni], a[0], b);
                mma_f16(acc[1][ni], a[1], b);
            }
        }
        __syncthreads();
        buf = (buf == 2) ? 0 : buf + 1;
    }

    // epilogue: fp16 [m][o], half2 stores
    uint32_t* outp = (uint32_t*)g_xw;
#pragma unroll
    for (int ni = 0; ni < 4; ni++) {
        int col2 = wc * 16 + ni * 4 + tig;
#pragma unroll
        for (int mi = 0; mi < 2; mi++) {
            int row = m0 + wr * 32 + mi * 16 + g;
            outp[(size_t)row * 64 + col2] = pack_h2(acc[mi][ni][0], acc[mi][ni][1]);
            outp[(size_t)(row + 8) * 64 + col2] = pack_h2(acc[mi][ni][2], acc[mi][ni][3]);
        }
    }
}

// =====================================================================
// k_main: per batch C = A @ XW (fp16 mma), 3-stage pipeline; grid (8,32).
// smem: As 3 x [128][40] fp32 (61440B) | Bs 3 x [32][136] fp16 (26112B) | degs
// =====================================================================
#define AS3 61440
#define BS3 26112
#define MAIN_SMEM (AS3 + BS3 + 512)

__global__ __launch_bounds__(256, 2) void k_main(const float* __restrict__ A,
                                                 const float* __restrict__ bias,
                                                 float* __restrict__ out) {
    extern __shared__ float sm[];
    char* smc = (char*)sm;
    const float2* As2 = (const float2*)sm;
    float* degs = (float*)(smc + AS3 + BS3);
    const uint32_t as_a = su32(sm), bs_a = su32(smc + AS3);

    const int tid = threadIdx.x, lane = tid & 31, wid = tid >> 5;
    const int g = lane >> 2, tig = lane & 3;
    const int wr = wid & 3, wc = wid >> 2;
    const int m0 = blockIdx.x * 128, bz = blockIdx.y;
    const float* Ab = A + (size_t)bz * 1024 * 1024;
    const __half* Bp = g_xw + (size_t)bz * 131072;

    const int lr = tid >> 3, lc4 = tid & 7;

    auto loadT = [&](int buf, int s) {
#pragma unroll
        for (int i = 0; i < 4; i++) {
            int row = lr + i * 32;
            cp16(as_a + (uint32_t)((buf * 128 + row) * AP + lc4 * 4) * 4,
                 Ab + (size_t)(m0 + row) * 1024 + s * 32 + lc4 * 4);
        }
        const char* src = (const char*)(Bp + s * 32 * 128);
#pragma unroll
        for (int i = 0; i < 2; i++) {
            int gi = tid + i * 256;
            int r = gi >> 4, c = gi & 15;
            cp16(bs_a + (uint32_t)(buf * 8704 + r * 272 + c * 16),
                 src + r * 256 + c * 16);
        }
        cp_commit();
    };

    float acc[2][8][4];
#pragma unroll
    for (int mi = 0; mi < 2; mi++)
#pragma unroll
        for (int ni = 0; ni < 8; ni++)
#pragma unroll
            for (int q = 0; q < 4; q++) acc[mi][ni][q] = 0.0f;
    float dg[2][2] = {{0.0f, 0.0f}, {0.0f, 0.0f}};

    loadT(0, 0);
    loadT(1, 1);

    const int lm_k = lane & 15;
    const int lm_n8 = (lane >> 4) * 8;

    int buf = 0;
    for (int s = 0; s < 32; s++) {
        if (s < 30) {
            loadT(buf == 0 ? 2 : buf - 1, s + 2);  // (s+2)%3
            cp_wait<2>();
        } else if (s == 30) cp_wait<1>();
        else cp_wait<0>();
        __syncthreads();
        const uint32_t bsb = bs_a + buf * 8704;

#pragma unroll
        for (int h = 0; h < 2; h++) {
            uint32_t a[2][4];
#pragma unroll
            for (int mi = 0; mi < 2; mi++) {
                int row = wr * 32 + mi * 16 + g;
                int base = (buf * 128 + row) * (AP / 2) + h * 8 + tig;
                float2 u0 = As2[base];
                float2 u1 = As2[base + 8 * (AP / 2)];
                float2 u2 = As2[base + 4];
                float2 u3 = As2[base + 8 * (AP / 2) + 4];
                a[mi][0] = pack_h2(u0.x, u0.y);
                a[mi][1] = pack_h2(u1.x, u1.y);
                a[mi][2] = pack_h2(u2.x, u2.y);
                a[mi][3] = pack_h2(u3.x, u3.y);
                if (wc == 0) {
                    dg[mi][0] += (u0.x + u0.y) + (u2.x + u2.y);
                    dg[mi][1] += (u1.x + u1.y) + (u3.x + u3.y);
                }
            }
            uint32_t bfr[4][4];
#pragma unroll
            for (int j = 0; j < 4; j++) {
                int n0 = wc * 64 + j * 16 + lm_n8;
                uint32_t addr = bsb + (uint32_t)((h * 16 + lm_k) * 272 + n0 * 2);
                ldmat4t(bfr[j], addr);
            }
#pragma unroll
            for (int ni = 0; ni < 8; ni++) {
                const uint32_t* b = &bfr[ni >> 1][(ni & 1) * 2];
                mma_f16(acc[0][ni], a[0], b);
                mma_f16(acc[1][ni], a[1], b);
            }
        }
        __syncthreads();
        buf = (buf == 2) ? 0 : buf + 1;
    }

    if (wc == 0) {
#pragma unroll
        for (int mi = 0; mi < 2; mi++)
#pragma unroll
            for (int r = 0; r < 2; r++) {
                float v = dg[mi][r];
                v += __shfl_xor_sync(0xffffffffu, v, 1);
                v += __shfl_xor_sync(0xffffffffu, v, 2);
                if (tig == 0) degs[wr * 32 + mi * 16 + r * 8 + g] = v;
            }
    }
    __syncthreads();

    float inv[2][2];
#pragma unroll
    for (int mi = 0; mi < 2; mi++) {
        inv[mi][0] = 1.0f / degs[wr * 32 + mi * 16 + g];
        inv[mi][1] = 1.0f / degs[wr * 32 + mi * 16 + g + 8];
    }

#pragma unroll
    for (int ni = 0; ni < 8; ni++) {
        int col = wc * 64 + ni * 8 + tig * 2;
        float2 bv = *(const float2*)(bias + col);
#pragma unroll
        for (int mi = 0; mi < 2; mi++) {
            int row = m0 + wr * 32 + mi * 16 + g;
            float2 v0, v1;
            v0.x = leaky(fmaf(acc[mi][ni][0], inv[mi][0], bv.x));
            v0.y = leaky(fmaf(acc[mi][ni][1], inv[mi][0], bv.y));
            v1.x = leaky(fmaf(acc[mi][ni][2], inv[mi][1], bv.x));
            v1.y = leaky(fmaf(acc[mi][ni][3], inv[mi][1], bv.y));
            *(float2*)(out + ((size_t)bz * 1024 + row) * 128 + col) = v0;
            *(float2*)(out + ((size_t)bz * 1024 + row + 8) * 128 + col) = v1;
        }
    }
}

// ---------------- host ----------------
extern "C" void kernel_launch(void* const* d_in, const int* in_sizes, int n_in,
                              void* d_out, int out_size) {
    const float* X    = (const float*)d_in[0];  // [32,1024,128]
    const float* adj  = (const float*)d_in[1];  // [32,1024,1024]
    const float* W    = (const float*)d_in[2];  // [128,128]
    const float* bias = (const float*)d_in[3];  // [128]
    float* out = (float*)d_out;                 // [32,1024,128]

    static int inited = 0;
    if (!inited) {
        cudaFuncSetAttribute(k_xw, cudaFuncAttributeMaxDynamicSharedMemorySize, XW_SMEM);
        cudaFuncSetAttribute(k_main, cudaFuncAttributeMaxDynamicSharedMemorySize, MAIN_SMEM);
        inited = 1;
    }

    k_xw<<<512, 256, XW_SMEM>>>(X, W);
    k_main<<<dim3(8, 32), 256, MAIN_SMEM>>>(adj, bias, out);
}